// round 3
// baseline (speedup 1.0000x reference)
#include <cuda_runtime.h>
#include <cstdint>

#define BB 32
#define NN 100
#define HH 128
#define BIN 16

// scratch (no allocation allowed)
__device__ float g_A[BB * NN * HH];   // local_feats @ W_apair
__device__ float g_gf[BB * NN * HH];  // global_feats

// ---------------------------------------------------------------------------
// Kernel 1: A[row, k] = sum_h local[row, h] * W_apair[h, k]   (row = b*N+i)
// ---------------------------------------------------------------------------
__global__ void k_compute_A(
    const float* __restrict__ local, const float* __restrict__ W) {
    int row = blockIdx.x;
    int k = threadIdx.x;
    __shared__ float sh[HH];
    sh[k] = local[row * HH + k];
    __syncthreads();
    float acc = 0.f;
#pragma unroll 8
    for (int h = 0; h < HH; h++) acc = fmaf(sh[h], W[h * HH + k], acc);
    g_A[row * HH + k] = acc;
}

// ---------------------------------------------------------------------------
// Kernel 2: per block (b,i):
//   phase A: s[j] = sigmoid( sum_h relu(A_i[h]+A_j[h]+bb[h]+(bin@Wb)[h]) * Watt[h] + batt )
//   phase B: gf[b,i,h] = sum_j s[j] * local[b,j,h]
// ---------------------------------------------------------------------------
__global__ void k_main(
    const float* __restrict__ local, const float* __restrict__ bin,
    const float* __restrict__ Wb, const float* __restrict__ bb,
    const float* __restrict__ Watt, const float* __restrict__ batt) {
    const int i = blockIdx.x;
    const int b = blockIdx.y;
    const int tid = threadIdx.x;
    const int w = tid >> 5;
    const int l = tid & 31;
    const int base = b * NN + i;

    __shared__ float s_sh[NN];
    __shared__ float part[256];

    // --- phase A: 8 warps, warp w handles j = w, w+8, ...; lane l owns h=4l..4l+3
    float wbr[BIN * 4];  // W_binary[c, 4l+q]
#pragma unroll
    for (int c = 0; c < BIN; c++) {
        float4 t = *(const float4*)&Wb[c * HH + 4 * l];
        wbr[4 * c + 0] = t.x; wbr[4 * c + 1] = t.y;
        wbr[4 * c + 2] = t.z; wbr[4 * c + 3] = t.w;
    }
    float4 ai = *(const float4*)&g_A[base * HH + 4 * l];
    {
        float4 bq = *(const float4*)&bb[4 * l];
        ai.x += bq.x; ai.y += bq.y; ai.z += bq.z; ai.w += bq.w;
    }
    float4 wa = *(const float4*)&Watt[4 * l];
    const float batt_v = batt[0];

    for (int j = w; j < NN; j += 8) {
        float4 aj = *(const float4*)&g_A[(b * NN + j) * HH + 4 * l];
        float a0 = ai.x + aj.x;
        float a1 = ai.y + aj.y;
        float a2 = ai.z + aj.z;
        float a3 = ai.w + aj.w;

        const float4* bp = (const float4*)&bin[(size_t)(base * NN + j) * BIN];
        float4 b0 = bp[0], b1 = bp[1], b2 = bp[2], b3 = bp[3];
        float bcv[BIN] = {b0.x, b0.y, b0.z, b0.w, b1.x, b1.y, b1.z, b1.w,
                          b2.x, b2.y, b2.z, b2.w, b3.x, b3.y, b3.z, b3.w};
#pragma unroll
        for (int c = 0; c < BIN; c++) {
            float bc = bcv[c];
            a0 = fmaf(bc, wbr[4 * c + 0], a0);
            a1 = fmaf(bc, wbr[4 * c + 1], a1);
            a2 = fmaf(bc, wbr[4 * c + 2], a2);
            a3 = fmaf(bc, wbr[4 * c + 3], a3);
        }
        float p = fmaxf(a0, 0.f) * wa.x;
        p = fmaf(fmaxf(a1, 0.f), wa.y, p);
        p = fmaf(fmaxf(a2, 0.f), wa.z, p);
        p = fmaf(fmaxf(a3, 0.f), wa.w, p);
#pragma unroll
        for (int off = 16; off; off >>= 1)
            p += __shfl_xor_sync(0xffffffffu, p, off);
        if (l == 0) {
            float z = p + batt_v;
            s_sh[j] = 1.f / (1.f + expf(-z));
        }
    }
    __syncthreads();

    // --- phase B: gf[b,i,h] = sum_j s[j]*local[b,j,h]; j split over 2 halves ---
    const int h = tid & 127;
    const int half = tid >> 7;
    const float* lp = local + (size_t)b * NN * HH + h;
    float g = 0.f;
    const int j0 = half * 50;
#pragma unroll 5
    for (int j = j0; j < j0 + 50; j++) g = fmaf(s_sh[j], lp[j * HH], g);
    part[tid] = g;
    __syncthreads();
    if (tid < 128) g_gf[base * HH + tid] = part[tid] + part[tid + 128];
}

// ---------------------------------------------------------------------------
// Kernel 3: gather. out[0:E*H] = local_pair_g, out[E*H:2*E*H] = global_pair
// sparse_idx is int32 (JAX canonicalizes int64->int32 with x64 disabled).
// Indices clamped so a wrong dtype inference shows up as rel_err, not a trap.
// ---------------------------------------------------------------------------
__global__ void k_gather(
    const float* __restrict__ local, const int* __restrict__ idx,
    float* __restrict__ out, int E) {
    int e = blockIdx.x * 2 + (threadIdx.x >> 7);
    int h = threadIdx.x & 127;
    if (e >= E) return;
    int b  = min(max(idx[e * 3 + 0], 0), BB - 1);
    int ii = min(max(idx[e * 3 + 1], 0), NN - 1);
    int jj = min(max(idx[e * 3 + 2], 0), NN - 1);
    int ri = (b * NN + ii) * HH + h;
    int rj = (b * NN + jj) * HH + h;
    out[(size_t)e * HH + h] = local[ri] + local[rj];
    out[(size_t)E * HH + (size_t)e * HH + h] = g_gf[ri] + g_gf[rj];
}

// ---------------------------------------------------------------------------
extern "C" void kernel_launch(void* const* d_in, const int* in_sizes, int n_in,
                              void* d_out, int out_size) {
    const float* local    = (const float*)d_in[0];  // (32,100,128)
    const float* bin      = (const float*)d_in[1];  // (32,100,100,16)
    const int*   sidx     = (const int*)d_in[2];    // (E,3) int32
    const float* W_apair  = (const float*)d_in[3];  // (128,128)
    const float* W_binary = (const float*)d_in[4];  // (16,128)
    const float* b_binary = (const float*)d_in[5];  // (128)
    const float* W_att    = (const float*)d_in[6];  // (128,1)
    const float* b_att    = (const float*)d_in[7];  // (1)
    float* out = (float*)d_out;
    const int E = in_sizes[2] / 3;

    k_compute_A<<<BB * NN, 128>>>(local, W_apair);
    dim3 grid2(NN, BB);
    k_main<<<grid2, 256>>>(local, bin, W_binary, b_binary, W_att, b_att);
    k_gather<<<(E + 1) / 2, 256>>>(local, sidx, out, E);
}

// round 4
// speedup vs baseline: 1.1058x; 1.1058x over previous
#include <cuda_runtime.h>
#include <cstdint>

#define BB 32
#define NN 100
#define HH 128
#define BIN 16

// scratch (no allocation allowed)
__device__ float g_A[BB * NN * HH];   // local_feats @ W_apair
__device__ float g_gf[BB * NN * HH];  // global_feats

// ---------------------------------------------------------------------------
// Kernel 1: A = local(3200x128) @ W(128x128).
// 100 blocks x 256 threads; each block computes 32 rows; W streamed from L1/L2
// once per block (6.4 MB total L2 traffic instead of 200 MB).
// Thread (kq = t&31, rg = t>>5) owns 4 rows x 4 cols (float4).
// ---------------------------------------------------------------------------
__global__ void k_compute_A(
    const float* __restrict__ local, const float* __restrict__ W) {
    __shared__ float ls[32][HH];  // 16 KB row tile
    const int tid = threadIdx.x;
    const int r0 = blockIdx.x * 32;

    const float4* src = (const float4*)&local[r0 * HH];
    float4* dst = (float4*)&ls[0][0];
#pragma unroll
    for (int t = tid; t < 32 * HH / 4; t += 256) dst[t] = src[t];
    __syncthreads();

    const int kq = tid & 31;
    const int rg = tid >> 5;
    float4 acc0 = {0,0,0,0}, acc1 = {0,0,0,0}, acc2 = {0,0,0,0}, acc3 = {0,0,0,0};
#pragma unroll 4
    for (int h = 0; h < HH; h++) {
        float4 wv = *(const float4*)&W[h * HH + 4 * kq];
        float l0 = ls[rg * 4 + 0][h];
        float l1 = ls[rg * 4 + 1][h];
        float l2 = ls[rg * 4 + 2][h];
        float l3 = ls[rg * 4 + 3][h];
        acc0.x = fmaf(l0, wv.x, acc0.x); acc0.y = fmaf(l0, wv.y, acc0.y);
        acc0.z = fmaf(l0, wv.z, acc0.z); acc0.w = fmaf(l0, wv.w, acc0.w);
        acc1.x = fmaf(l1, wv.x, acc1.x); acc1.y = fmaf(l1, wv.y, acc1.y);
        acc1.z = fmaf(l1, wv.z, acc1.z); acc1.w = fmaf(l1, wv.w, acc1.w);
        acc2.x = fmaf(l2, wv.x, acc2.x); acc2.y = fmaf(l2, wv.y, acc2.y);
        acc2.z = fmaf(l2, wv.z, acc2.z); acc2.w = fmaf(l2, wv.w, acc2.w);
        acc3.x = fmaf(l3, wv.x, acc3.x); acc3.y = fmaf(l3, wv.y, acc3.y);
        acc3.z = fmaf(l3, wv.z, acc3.z); acc3.w = fmaf(l3, wv.w, acc3.w);
    }
    *(float4*)&g_A[(r0 + rg * 4 + 0) * HH + 4 * kq] = acc0;
    *(float4*)&g_A[(r0 + rg * 4 + 1) * HH + 4 * kq] = acc1;
    *(float4*)&g_A[(r0 + rg * 4 + 2) * HH + 4 * kq] = acc2;
    *(float4*)&g_A[(r0 + rg * 4 + 3) * HH + 4 * kq] = acc3;
}

// ---------------------------------------------------------------------------
// Kernel 2: per block (b,i):
//   phase A: s[j] = sigmoid( relu(A_i + A_j + bb + bin@Wb) . Watt + batt )
//            bin tile staged in smem (one coalesced load, broadcast LDS after)
//   phase B: gf[b,i,h] = sum_j s[j] * local[b,j,h]
// ---------------------------------------------------------------------------
__global__ void k_main(
    const float* __restrict__ local, const float* __restrict__ bin,
    const float* __restrict__ Wb, const float* __restrict__ bb,
    const float* __restrict__ Watt, const float* __restrict__ batt) {
    const int i = blockIdx.x;
    const int b = blockIdx.y;
    const int tid = threadIdx.x;
    const int w = tid >> 5;
    const int l = tid & 31;
    const int base = b * NN + i;

    __shared__ float4 bin_sh[NN * 4];  // 100 x 16 floats = 6.4 KB
    __shared__ float s_sh[NN];
    __shared__ float part[256];

    // coopeartive coalesced load of the bin tile for (b,i)
    const float4* bsrc = (const float4*)&bin[(size_t)base * NN * BIN];
#pragma unroll
    for (int t = tid; t < NN * 4; t += 256) bin_sh[t] = bsrc[t];

    // lane l owns h = 4l..4l+3
    float wbr[BIN * 4];
#pragma unroll
    for (int c = 0; c < BIN; c++) {
        float4 t = *(const float4*)&Wb[c * HH + 4 * l];
        wbr[4 * c + 0] = t.x; wbr[4 * c + 1] = t.y;
        wbr[4 * c + 2] = t.z; wbr[4 * c + 3] = t.w;
    }
    float4 ai = *(const float4*)&g_A[base * HH + 4 * l];
    {
        float4 bq = *(const float4*)&bb[4 * l];
        ai.x += bq.x; ai.y += bq.y; ai.z += bq.z; ai.w += bq.w;
    }
    float4 wa = *(const float4*)&Watt[4 * l];
    const float batt_v = batt[0];
    __syncthreads();

    for (int j = w; j < NN; j += 8) {
        float4 aj = *(const float4*)&g_A[(b * NN + j) * HH + 4 * l];
        float a0 = ai.x + aj.x;
        float a1 = ai.y + aj.y;
        float a2 = ai.z + aj.z;
        float a3 = ai.w + aj.w;

        float4 b0 = bin_sh[j * 4 + 0];
        float4 b1 = bin_sh[j * 4 + 1];
        float4 b2 = bin_sh[j * 4 + 2];
        float4 b3 = bin_sh[j * 4 + 3];
        float bcv[BIN] = {b0.x, b0.y, b0.z, b0.w, b1.x, b1.y, b1.z, b1.w,
                          b2.x, b2.y, b2.z, b2.w, b3.x, b3.y, b3.z, b3.w};
#pragma unroll
        for (int c = 0; c < BIN; c++) {
            float bc = bcv[c];
            a0 = fmaf(bc, wbr[4 * c + 0], a0);
            a1 = fmaf(bc, wbr[4 * c + 1], a1);
            a2 = fmaf(bc, wbr[4 * c + 2], a2);
            a3 = fmaf(bc, wbr[4 * c + 3], a3);
        }
        float p = fmaxf(a0, 0.f) * wa.x;
        p = fmaf(fmaxf(a1, 0.f), wa.y, p);
        p = fmaf(fmaxf(a2, 0.f), wa.z, p);
        p = fmaf(fmaxf(a3, 0.f), wa.w, p);
#pragma unroll
        for (int off = 16; off; off >>= 1)
            p += __shfl_xor_sync(0xffffffffu, p, off);
        if (l == 0) {
            float z = p + batt_v;
            s_sh[j] = 1.f / (1.f + __expf(-z));
        }
    }
    __syncthreads();

    // --- phase B: gf[b,i,h] = sum_j s[j]*local[b,j,h]; j split over 2 halves ---
    const int h = tid & 127;
    const int half = tid >> 7;
    const float* lp = local + (size_t)b * NN * HH + h;
    float g = 0.f;
    const int j0 = half * 50;
#pragma unroll 5
    for (int j = j0; j < j0 + 50; j++) g = fmaf(s_sh[j], lp[j * HH], g);
    part[tid] = g;
    __syncthreads();
    if (tid < 128) g_gf[base * HH + tid] = part[tid] + part[tid + 128];
}

// ---------------------------------------------------------------------------
// Kernel 3: gather (float4). out[0:E*H] = local_pair_g, out[E*H:] = global_pair
// sparse_idx is int32 (JAX canonicalizes int64->int32). Clamped defensively.
// ---------------------------------------------------------------------------
__global__ void k_gather(
    const float* __restrict__ local, const int* __restrict__ idx,
    float* __restrict__ out, int E) {
    int e = blockIdx.x * 8 + (threadIdx.x >> 5);
    int q = threadIdx.x & 31;  // float4 group: h = 4q..4q+3
    if (e >= E) return;
    int b  = min(max(idx[e * 3 + 0], 0), BB - 1);
    int ii = min(max(idx[e * 3 + 1], 0), NN - 1);
    int jj = min(max(idx[e * 3 + 2], 0), NN - 1);
    int ri = (b * NN + ii) * HH + 4 * q;
    int rj = (b * NN + jj) * HH + 4 * q;
    float4 li = *(const float4*)&local[ri];
    float4 lj = *(const float4*)&local[rj];
    float4 gi = *(const float4*)&g_gf[ri];
    float4 gj = *(const float4*)&g_gf[rj];
    float4 o1 = {li.x + lj.x, li.y + lj.y, li.z + lj.z, li.w + lj.w};
    float4 o2 = {gi.x + gj.x, gi.y + gj.y, gi.z + gj.z, gi.w + gj.w};
    *(float4*)&out[(size_t)e * HH + 4 * q] = o1;
    *(float4*)&out[(size_t)E * HH + (size_t)e * HH + 4 * q] = o2;
}

// ---------------------------------------------------------------------------
extern "C" void kernel_launch(void* const* d_in, const int* in_sizes, int n_in,
                              void* d_out, int out_size) {
    const float* local    = (const float*)d_in[0];  // (32,100,128)
    const float* bin      = (const float*)d_in[1];  // (32,100,100,16)
    const int*   sidx     = (const int*)d_in[2];    // (E,3) int32
    const float* W_apair  = (const float*)d_in[3];  // (128,128)
    const float* W_binary = (const float*)d_in[4];  // (16,128)
    const float* b_binary = (const float*)d_in[5];  // (128)
    const float* W_att    = (const float*)d_in[6];  // (128,1)
    const float* b_att    = (const float*)d_in[7];  // (1)
    float* out = (float*)d_out;
    const int E = in_sizes[2] / 3;

    k_compute_A<<<BB * NN / 32, 256>>>(local, W_apair);
    dim3 grid2(NN, BB);
    k_main<<<grid2, 256>>>(local, bin, W_binary, b_binary, W_att, b_att);
    k_gather<<<(E + 7) / 8, 256>>>(local, sidx, out, E);
}

// round 6
// speedup vs baseline: 1.2003x; 1.0854x over previous
#include <cuda_runtime.h>
#include <cstdint>

#define BB 32
#define NN 100
#define HH 128
#define BIN 16

// scratch (no allocation allowed)
__device__ float g_A[BB * NN * HH];   // local_feats @ W_apair
__device__ float g_gf[BB * NN * HH];  // global_feats

// ---- packed f32x2 helpers (Blackwell; only reachable via PTX) --------------
typedef unsigned long long u64;
__device__ __forceinline__ u64 pk2(float lo, float hi) {
    u64 r; asm("mov.b64 %0, {%1, %2};" : "=l"(r) : "f"(lo), "f"(hi)); return r;
}
__device__ __forceinline__ void upk2(u64 v, float& lo, float& hi) {
    asm("mov.b64 {%0, %1}, %2;" : "=f"(lo), "=f"(hi) : "l"(v));
}
__device__ __forceinline__ u64 fma2(u64 a, u64 b, u64 c) {
    u64 d; asm("fma.rn.f32x2 %0, %1, %2, %3;" : "=l"(d) : "l"(a), "l"(b), "l"(c)); return d;
}
__device__ __forceinline__ u64 add2(u64 a, u64 b) {
    u64 d; asm("add.rn.f32x2 %0, %1, %2;" : "=l"(d) : "l"(a), "l"(b)); return d;
}

// ---------------------------------------------------------------------------
// Kernel 1: A = local(3200x128) @ W(128x128).
// 400 blocks x 256 threads, 8 rows/block: enough CTAs for all SMs AND modest
// W re-read traffic (400 x 64KB = 25.6 MB L2). Thread = (row rg, col quad kq).
// ---------------------------------------------------------------------------
__global__ void k_compute_A(
    const float* __restrict__ local, const float* __restrict__ W) {
    __shared__ float ls[8][HH];  // 4 KB row tile
    const int tid = threadIdx.x;
    const int r0 = blockIdx.x * 8;

    ((float4*)ls)[tid] = ((const float4*)&local[r0 * HH])[tid];
    __syncthreads();

    const int kq = tid & 31;   // col quad: 4kq..4kq+3
    const int rg = tid >> 5;   // row 0..7
    float4 acc = {0.f, 0.f, 0.f, 0.f};
#pragma unroll 8
    for (int h = 0; h < HH; h++) {
        float4 wv = *(const float4*)&W[h * HH + 4 * kq];
        float lv = ls[rg][h];
        acc.x = fmaf(lv, wv.x, acc.x);
        acc.y = fmaf(lv, wv.y, acc.y);
        acc.z = fmaf(lv, wv.z, acc.z);
        acc.w = fmaf(lv, wv.w, acc.w);
    }
    *(float4*)&g_A[(r0 + rg) * HH + 4 * kq] = acc;
}

// ---------------------------------------------------------------------------
// Kernel 2: per block (b,i):
//   phase A: s[j] = sigmoid( relu(A_i + A_j + bb + bin@Wb) . Watt + batt )
//            inner GEMM in packed f32x2 (2 indep chains per packed acc)
//   phase B: gf[b,i,h] = sum_j s[j] * local[b,j,h]
// ---------------------------------------------------------------------------
__global__ void k_main(
    const float* __restrict__ local, const float* __restrict__ bin,
    const float* __restrict__ Wb, const float* __restrict__ bb,
    const float* __restrict__ Watt, const float* __restrict__ batt) {
    const int i = blockIdx.x;
    const int b = blockIdx.y;
    const int tid = threadIdx.x;
    const int w = tid >> 5;
    const int l = tid & 31;
    const int base = b * NN + i;

    __shared__ float4 bin_sh[NN * 4];  // 6.4 KB
    __shared__ float s_sh[NN];
    __shared__ float part[256];

    const float4* bsrc = (const float4*)&bin[(size_t)base * NN * BIN];
#pragma unroll
    for (int t = tid; t < NN * 4; t += 256) bin_sh[t] = bsrc[t];

    // lane l owns h = 4l..4l+3, as two packed pairs (01, 23)
    u64 wpk[BIN * 2];  // wpk[2c] = Wb[c][4l],Wb[c][4l+1]; wpk[2c+1] = z,w
#pragma unroll
    for (int c = 0; c < BIN; c++) {
        float4 t = *(const float4*)&Wb[c * HH + 4 * l];
        wpk[2 * c + 0] = pk2(t.x, t.y);
        wpk[2 * c + 1] = pk2(t.z, t.w);
    }
    u64 ai01, ai23;
    {
        float4 a = *(const float4*)&g_A[base * HH + 4 * l];
        float4 q = *(const float4*)&bb[4 * l];
        ai01 = pk2(a.x + q.x, a.y + q.y);
        ai23 = pk2(a.z + q.z, a.w + q.w);
    }
    float4 wa = *(const float4*)&Watt[4 * l];
    const float batt_v = batt[0];
    __syncthreads();

    for (int j = w; j < NN; j += 8) {
        float4 aj = *(const float4*)&g_A[(b * NN + j) * HH + 4 * l];
        u64 s01 = add2(ai01, pk2(aj.x, aj.y));
        u64 s23 = add2(ai23, pk2(aj.z, aj.w));
        u64 t01 = 0, t23 = 0;  // second chains (0.0f x2 bit pattern = 0)

        float4 b0 = bin_sh[j * 4 + 0];
        float4 b1 = bin_sh[j * 4 + 1];
        float4 b2 = bin_sh[j * 4 + 2];
        float4 b3 = bin_sh[j * 4 + 3];
        float bcv[BIN] = {b0.x, b0.y, b0.z, b0.w, b1.x, b1.y, b1.z, b1.w,
                          b2.x, b2.y, b2.z, b2.w, b3.x, b3.y, b3.z, b3.w};
#pragma unroll
        for (int c = 0; c < BIN; c += 2) {
            u64 p0 = pk2(bcv[c], bcv[c]);
            u64 p1 = pk2(bcv[c + 1], bcv[c + 1]);
            s01 = fma2(p0, wpk[2 * c + 0], s01);
            s23 = fma2(p0, wpk[2 * c + 1], s23);
            t01 = fma2(p1, wpk[2 * c + 2], t01);
            t23 = fma2(p1, wpk[2 * c + 3], t23);
        }
        s01 = add2(s01, t01);
        s23 = add2(s23, t23);
        float a0, a1, a2, a3;
        upk2(s01, a0, a1);
        upk2(s23, a2, a3);

        float p = fmaxf(a0, 0.f) * wa.x;
        p = fmaf(fmaxf(a1, 0.f), wa.y, p);
        p = fmaf(fmaxf(a2, 0.f), wa.z, p);
        p = fmaf(fmaxf(a3, 0.f), wa.w, p);
#pragma unroll
        for (int off = 16; off; off >>= 1)
            p += __shfl_xor_sync(0xffffffffu, p, off);
        if (l == 0) {
            float z = p + batt_v;
            s_sh[j] = 1.f / (1.f + __expf(-z));
        }
    }
    __syncthreads();

    // --- phase B: gf[b,i,h] = sum_j s[j]*local[b,j,h]; j split over 2 halves ---
    const int h = tid & 127;
    const int half = tid >> 7;
    const float* lp = local + (size_t)b * NN * HH + h;
    float g = 0.f;
    const int j0 = half * 50;
#pragma unroll 5
    for (int j = j0; j < j0 + 50; j++) g = fmaf(s_sh[j], lp[j * HH], g);
    part[tid] = g;
    __syncthreads();
    if (tid < 128) g_gf[base * HH + tid] = part[tid] + part[tid + 128];
}

// ---------------------------------------------------------------------------
// Kernel 3: gather (float4). out[0:E*H] = local_pair_g, out[E*H:] = global_pair
// ---------------------------------------------------------------------------
__global__ void k_gather(
    const float* __restrict__ local, const int* __restrict__ idx,
    float* __restrict__ out, int E) {
    int e = blockIdx.x * 8 + (threadIdx.x >> 5);
    int q = threadIdx.x & 31;
    if (e >= E) return;
    int b  = min(max(idx[e * 3 + 0], 0), BB - 1);
    int ii = min(max(idx[e * 3 + 1], 0), NN - 1);
    int jj = min(max(idx[e * 3 + 2], 0), NN - 1);
    int ri = (b * NN + ii) * HH + 4 * q;
    int rj = (b * NN + jj) * HH + 4 * q;
    float4 li = *(const float4*)&local[ri];
    float4 lj = *(const float4*)&local[rj];
    float4 gi = *(const float4*)&g_gf[ri];
    float4 gj = *(const float4*)&g_gf[rj];
    float4 o1 = {li.x + lj.x, li.y + lj.y, li.z + lj.z, li.w + lj.w};
    float4 o2 = {gi.x + gj.x, gi.y + gj.y, gi.z + gj.z, gi.w + gj.w};
    *(float4*)&out[(size_t)e * HH + 4 * q] = o1;
    *(float4*)&out[(size_t)E * HH + (size_t)e * HH + 4 * q] = o2;
}

// ---------------------------------------------------------------------------
extern "C" void kernel_launch(void* const* d_in, const int* in_sizes, int n_in,
                              void* d_out, int out_size) {
    const float* local    = (const float*)d_in[0];  // (32,100,128)
    const float* bin      = (const float*)d_in[1];  // (32,100,100,16)
    const int*   sidx     = (const int*)d_in[2];    // (E,3) int32
    const float* W_apair  = (const float*)d_in[3];  // (128,128)
    const float* W_binary = (const float*)d_in[4];  // (16,128)
    const float* b_binary = (const float*)d_in[5];  // (128)
    const float* W_att    = (const float*)d_in[6];  // (128,1)
    const float* b_att    = (const float*)d_in[7];  // (1)
    float* out = (float*)d_out;
    const int E = in_sizes[2] / 3;

    k_compute_A<<<BB * NN / 8, 256>>>(local, W_apair);
    dim3 grid2(NN, BB);
    k_main<<<grid2, 256>>>(local, bin, W_binary, b_binary, W_att, b_att);
    k_gather<<<(E + 7) / 8, 256>>>(local, sidx, out, E);
}

// round 7
// speedup vs baseline: 1.5746x; 1.3119x over previous
#include <cuda_runtime.h>
#include <cstdint>

#define BB 32
#define NN 100
#define HH 128
#define BIN 16

// scratch (no allocation allowed)
__device__ float g_A[BB * NN * HH];   // local_feats @ W_apair
__device__ float g_gf[BB * NN * HH];  // global_feats

// ---- packed f32x2 helpers (Blackwell; only reachable via PTX) --------------
typedef unsigned long long u64;
__device__ __forceinline__ u64 pk2(float lo, float hi) {
    u64 r; asm("mov.b64 %0, {%1, %2};" : "=l"(r) : "f"(lo), "f"(hi)); return r;
}
__device__ __forceinline__ void upk2(u64 v, float& lo, float& hi) {
    asm("mov.b64 {%0, %1}, %2;" : "=f"(lo), "=f"(hi) : "l"(v));
}
__device__ __forceinline__ u64 fma2(u64 a, u64 b, u64 c) {
    u64 d; asm("fma.rn.f32x2 %0, %1, %2, %3;" : "=l"(d) : "l"(a), "l"(b), "l"(c)); return d;
}
__device__ __forceinline__ u64 add2(u64 a, u64 b) {
    u64 d; asm("add.rn.f32x2 %0, %1, %2;" : "=l"(d) : "l"(a), "l"(b)); return d;
}

// ---------------------------------------------------------------------------
// Kernel 1: A = local(3200x128) @ W(128x128).
// 800 blocks x 128 threads. Thread = column `col`, 4 rows: each W value loaded
// once feeds 4 FMAs; 8 independent acc chains (4 rows x 2 h-halves).
// ---------------------------------------------------------------------------
__global__ void k_compute_A(
    const float* __restrict__ local, const float* __restrict__ W) {
    __shared__ float ls[4][HH];  // 2 KB
    const int tid = threadIdx.x;
    const int r0 = blockIdx.x * 4;

    ((float4*)ls)[tid] = ((const float4*)&local[r0 * HH])[tid];
    __syncthreads();

    const int col = tid;
    float a0 = 0.f, a1 = 0.f, a2 = 0.f, a3 = 0.f;
    float c0 = 0.f, c1 = 0.f, c2 = 0.f, c3 = 0.f;
#pragma unroll 8
    for (int h = 0; h < HH; h += 2) {
        float w0 = W[h * HH + col];
        float w1 = W[(h + 1) * HH + col];
        a0 = fmaf(ls[0][h], w0, a0); c0 = fmaf(ls[0][h + 1], w1, c0);
        a1 = fmaf(ls[1][h], w0, a1); c1 = fmaf(ls[1][h + 1], w1, c1);
        a2 = fmaf(ls[2][h], w0, a2); c2 = fmaf(ls[2][h + 1], w1, c2);
        a3 = fmaf(ls[3][h], w0, a3); c3 = fmaf(ls[3][h + 1], w1, c3);
    }
    g_A[(r0 + 0) * HH + col] = a0 + c0;
    g_A[(r0 + 1) * HH + col] = a1 + c1;
    g_A[(r0 + 2) * HH + col] = a2 + c2;
    g_A[(r0 + 3) * HH + col] = a3 + c3;
}

// ---------------------------------------------------------------------------
// Kernel 2: per block (b,i):
//   A1: lane partials of relu(A_i+A_j+bb+bin@Wb).Watt  -> part_sh (NO shfl;
//       j-iterations fully independent)
//   A2: thread-per-j sums 32 partials + sigmoid (100 parallel expf)
//   B : gf[b,i,h] = sum_j s[j] * local[b,j,h]
// ---------------------------------------------------------------------------
__global__ void k_main(
    const float* __restrict__ local, const float* __restrict__ bin,
    const float* __restrict__ Wb, const float* __restrict__ bb,
    const float* __restrict__ Watt, const float* __restrict__ batt) {
    const int i = blockIdx.x;
    const int b = blockIdx.y;
    const int tid = threadIdx.x;
    const int w = tid >> 5;
    const int l = tid & 31;
    const int base = b * NN + i;

    __shared__ float4 bin_sh[NN * 4];      // 6.4 KB
    __shared__ float part_sh[NN * 33];     // 13.2 KB, padded rows (33) vs bank conflicts
    __shared__ float s_sh[NN];
    __shared__ float part[256];

    const float4* bsrc = (const float4*)&bin[(size_t)base * NN * BIN];
#pragma unroll
    for (int t = tid; t < NN * 4; t += 256) bin_sh[t] = bsrc[t];

    // lane l owns h = 4l..4l+3, as two packed pairs (01, 23)
    u64 wpk[BIN * 2];
#pragma unroll
    for (int c = 0; c < BIN; c++) {
        float4 t = *(const float4*)&Wb[c * HH + 4 * l];
        wpk[2 * c + 0] = pk2(t.x, t.y);
        wpk[2 * c + 1] = pk2(t.z, t.w);
    }
    u64 ai01, ai23;
    {
        float4 a = *(const float4*)&g_A[base * HH + 4 * l];
        float4 q = *(const float4*)&bb[4 * l];
        ai01 = pk2(a.x + q.x, a.y + q.y);
        ai23 = pk2(a.z + q.z, a.w + q.w);
    }
    float4 wa = *(const float4*)&Watt[4 * l];
    const float batt_v = batt[0];
    __syncthreads();

    // --- A1: independent j iterations, no reduction ---
    for (int j = w; j < NN; j += 8) {
        float4 aj = *(const float4*)&g_A[(b * NN + j) * HH + 4 * l];
        u64 s01 = add2(ai01, pk2(aj.x, aj.y));
        u64 s23 = add2(ai23, pk2(aj.z, aj.w));
        u64 t01 = 0, t23 = 0;

        float4 b0 = bin_sh[j * 4 + 0];
        float4 b1 = bin_sh[j * 4 + 1];
        float4 b2 = bin_sh[j * 4 + 2];
        float4 b3 = bin_sh[j * 4 + 3];
        float bcv[BIN] = {b0.x, b0.y, b0.z, b0.w, b1.x, b1.y, b1.z, b1.w,
                          b2.x, b2.y, b2.z, b2.w, b3.x, b3.y, b3.z, b3.w};
#pragma unroll
        for (int c = 0; c < BIN; c += 2) {
            u64 p0 = pk2(bcv[c], bcv[c]);
            u64 p1 = pk2(bcv[c + 1], bcv[c + 1]);
            s01 = fma2(p0, wpk[2 * c + 0], s01);
            s23 = fma2(p0, wpk[2 * c + 1], s23);
            t01 = fma2(p1, wpk[2 * c + 2], t01);
            t23 = fma2(p1, wpk[2 * c + 3], t23);
        }
        s01 = add2(s01, t01);
        s23 = add2(s23, t23);
        float a0, a1, a2, a3;
        upk2(s01, a0, a1);
        upk2(s23, a2, a3);

        float p = fmaxf(a0, 0.f) * wa.x;
        p = fmaf(fmaxf(a1, 0.f), wa.y, p);
        p = fmaf(fmaxf(a2, 0.f), wa.z, p);
        p = fmaf(fmaxf(a3, 0.f), wa.w, p);
        part_sh[j * 33 + l] = p;
    }
    __syncthreads();

    // --- A2: thread-per-j final reduction + sigmoid (parallel across 100) ---
    if (tid < NN) {
        const float* pr = &part_sh[tid * 33];
        float s0 = 0.f, s1 = 0.f;
#pragma unroll
        for (int k = 0; k < 32; k += 2) {
            s0 += pr[k];
            s1 += pr[k + 1];
        }
        float z = s0 + s1 + batt_v;
        s_sh[tid] = 1.f / (1.f + __expf(-z));
    }
    __syncthreads();

    // --- B: gf[b,i,h] = sum_j s[j]*local[b,j,h]; j split over 2 halves ---
    const int h = tid & 127;
    const int half = tid >> 7;
    const float* lp = local + (size_t)b * NN * HH + h;
    float g = 0.f;
    const int j0 = half * 50;
#pragma unroll 5
    for (int j = j0; j < j0 + 50; j++) g = fmaf(s_sh[j], lp[j * HH], g);
    part[tid] = g;
    __syncthreads();
    if (tid < 128) g_gf[base * HH + tid] = part[tid] + part[tid + 128];
}

// ---------------------------------------------------------------------------
// Kernel 3: gather (float4). out[0:E*H] = local_pair_g, out[E*H:] = global_pair
// ---------------------------------------------------------------------------
__global__ void k_gather(
    const float* __restrict__ local, const int* __restrict__ idx,
    float* __restrict__ out, int E) {
    int e = blockIdx.x * 8 + (threadIdx.x >> 5);
    int q = threadIdx.x & 31;
    if (e >= E) return;
    int b  = min(max(idx[e * 3 + 0], 0), BB - 1);
    int ii = min(max(idx[e * 3 + 1], 0), NN - 1);
    int jj = min(max(idx[e * 3 + 2], 0), NN - 1);
    int ri = (b * NN + ii) * HH + 4 * q;
    int rj = (b * NN + jj) * HH + 4 * q;
    float4 li = *(const float4*)&local[ri];
    float4 lj = *(const float4*)&local[rj];
    float4 gi = *(const float4*)&g_gf[ri];
    float4 gj = *(const float4*)&g_gf[rj];
    float4 o1 = {li.x + lj.x, li.y + lj.y, li.z + lj.z, li.w + lj.w};
    float4 o2 = {gi.x + gj.x, gi.y + gj.y, gi.z + gj.z, gi.w + gj.w};
    *(float4*)&out[(size_t)e * HH + 4 * q] = o1;
    *(float4*)&out[(size_t)E * HH + (size_t)e * HH + 4 * q] = o2;
}

// ---------------------------------------------------------------------------
extern "C" void kernel_launch(void* const* d_in, const int* in_sizes, int n_in,
                              void* d_out, int out_size) {
    const float* local    = (const float*)d_in[0];  // (32,100,128)
    const float* bin      = (const float*)d_in[1];  // (32,100,100,16)
    const int*   sidx     = (const int*)d_in[2];    // (E,3) int32
    const float* W_apair  = (const float*)d_in[3];  // (128,128)
    const float* W_binary = (const float*)d_in[4];  // (16,128)
    const float* b_binary = (const float*)d_in[5];  // (128)
    const float* W_att    = (const float*)d_in[6];  // (128,1)
    const float* b_att    = (const float*)d_in[7];  // (1)
    float* out = (float*)d_out;
    const int E = in_sizes[2] / 3;

    k_compute_A<<<BB * NN / 4, 128>>>(local, W_apair);
    dim3 grid2(NN, BB);
    k_main<<<grid2, 256>>>(local, bin, W_binary, b_binary, W_att, b_att);
    k_gather<<<(E + 7) / 8, 256>>>(local, sidx, out, E);
}